// round 17
// baseline (speedup 1.0000x reference)
#include <cuda_runtime.h>
#include <cuda_fp16.h>
#include <cstdint>

// Per edge: out[o][t] = sum_k W[o][k] * x[k][t] + b[o],  O=K=64, T=256, E=10000
// mma.sync m16n8k16 f16 (both operands fp16, fp32 accumulate; rel ~2.9e-4).
// R17 (= R16 resubmit; R16 was an infra flake):
//   one CTA per HALF-edge, 4 CTAs/SM. D[o][t] = W * x (m=o, n=t).
//   Warp tile 16o x 64t. Epilogue: shfl-repair -> direct STG.128, NO smem
//   round-trip (saves 64KB L1/CTA + one barrier vs R15 champion).

#define T_DIM 256
#define K_DIM 64
#define O_DIM 64

// smem pitches (16B-chunk strides odd => conflict-free ldmatrix):
//   x: 136 f16 = 272B = 17 chunks;  W: 72 f16 = 144B = 9 chunks
#define WH_OFF   0u        // 64*144 = 9216
#define BIAS_OFF 9216u     // 256B, pad to 9472
#define XH_OFF   9472u     // 64*272 = 17408 -> 26880
#define SMEM_BYTES 26880

static __device__ __forceinline__ uint32_t s2u(const void* p) {
    uint32_t a;
    asm("{ .reg .u64 t; cvta.to.shared.u64 t, %1; cvt.u32.u64 %0, t; }" : "=r"(a) : "l"(p));
    return a;
}

// pack fp16(a), fp16(b) into one u32 (a -> low half)
static __device__ __forceinline__ uint32_t pack2h(float a, float b) {
    __half2 h = __floats2half2_rn(a, b);
    return *(uint32_t*)&h;
}

#define LDSM4(r, addr) \
    asm volatile("ldmatrix.sync.aligned.m8n8.x4.shared.b16 {%0,%1,%2,%3}, [%4];" \
        : "=r"((r)[0]), "=r"((r)[1]), "=r"((r)[2]), "=r"((r)[3]) : "r"(addr))

#define LDSM4T(r, addr) \
    asm volatile("ldmatrix.sync.aligned.m8n8.x4.trans.shared.b16 {%0,%1,%2,%3}, [%4];" \
        : "=r"((r)[0]), "=r"((r)[1]), "=r"((r)[2]), "=r"((r)[3]) : "r"(addr))

// A regs explicit (reordered from LDSM4), B = two regs
#define MMA_R(c, a0, a1, a2, a3, b0, b1) \
    asm volatile("mma.sync.aligned.m16n8k16.row.col.f32.f16.f16.f32 " \
        "{%0,%1,%2,%3}, {%4,%5,%6,%7}, {%8,%9}, {%0,%1,%2,%3};" \
        : "+f"((c)[0]), "+f"((c)[1]), "+f"((c)[2]), "+f"((c)[3]) \
        : "r"(a0), "r"(a1), "r"(a2), "r"(a3), "r"(b0), "r"(b1))

__global__ void __launch_bounds__(256, 4)
pl_hmma_shfl_kernel(const float* __restrict__ x, const float* __restrict__ W,
                    const float* __restrict__ b, float* __restrict__ out)
{
    extern __shared__ char base[];
    const uint32_t sb = s2u(base);

    const int tid = threadIdx.x, wid = tid >> 5, lane = tid & 31;
    const int e  = blockIdx.x >> 1;          // edge
    const int th = blockIdx.x & 1;           // t-half: siblings adjacent -> W L2-hits
    const float* xg = x + (size_t)e * (K_DIM * T_DIM) + th * 128;
    const float* wg = W + (size_t)e * (O_DIM * K_DIM);
    const float* bg = b + (size_t)e * O_DIM;
    float*       og = out + (size_t)e * (O_DIM * T_DIM) + th * 128;

    // ---- Stage W -> fp16, pitch 144B ----
    {
        const float4* wg4 = (const float4*)wg;
        #pragma unroll
        for (int i = 0; i < 4; i++) {
            const int f  = tid + (i << 8);         // 0..1023 float4s
            const int o  = f >> 4;
            const int kc = f & 15;
            float4 v = wg4[f];
            uint2 h;
            h.x = pack2h(v.x, v.y);
            h.y = pack2h(v.z, v.w);
            *(uint2*)(base + WH_OFF + (uint32_t)o * 144u + (uint32_t)kc * 8u) = h;
        }
    }
    // ---- Stage x half -> fp16, pitch 272B (128 t per row) ----
    {
        #pragma unroll
        for (int i = 0; i < 8; i++) {
            const int f  = tid + (i << 8);         // 0..2047 float4s
            const int k  = f >> 5;
            const int c4 = f & 31;
            float4 v = *(const float4*)(xg + (size_t)k * T_DIM + (c4 << 2));
            uint2 h;
            h.x = pack2h(v.x, v.y);
            h.y = pack2h(v.z, v.w);
            *(uint2*)(base + XH_OFF + (uint32_t)k * 272u + (uint32_t)c4 * 8u) = h;
        }
    }
    if (tid < 64) *(float*)(base + BIAS_OFF + tid * 4) = bg[tid];
    __syncthreads();

    // ---- Warp tile: o in [16*ow, +16), t in [64*tw, +64) ----
    const int ow = wid & 3, tw = wid >> 2;
    const int g = lane >> 2;           // fragment row within 8 (o)
    const int iq = lane & 3;           // col-pair index (t)
    const int lm = lane >> 3, lr = lane & 7;

    // c[nt][4]: rows o = 16ow + g (c0,c1) and 16ow + 8 + g (c2,c3),
    //           cols t = 64tw + 8nt + 2iq (+1)
    float c[8][4];
    {
        const float* bs = (const float*)(base + BIAS_OFF) + (ow << 4);
        const float b0 = bs[g];
        const float b1 = bs[8 + g];
        #pragma unroll
        for (int nt = 0; nt < 8; nt++) {
            c[nt][0] = b0; c[nt][1] = b0;
            c[nt][2] = b1; c[nt][3] = b1;
        }
    }

    #pragma unroll
    for (int ks = 0; ks < 4; ks++) {
        // A frags (W, non-trans): x4 regs (o,k0)(o,k8)(o+8,k0)(o+8,k8)
        //   -> A order = {w[0], w[2], w[1], w[3]}   (validated in R11)
        const int orow = (ow << 4) + ((lm & 2) ? 8 : 0) + lr;
        const int kcol = ks * 16 + ((lm & 1) ? 8 : 0);
        uint32_t wh[4];
        LDSM4(wh, sb + WH_OFF + (uint32_t)orow * 144u + (uint32_t)kcol * 2u);

        #pragma unroll
        for (int p = 0; p < 4; p++) {
            // B frags (x, trans): x4 mats -> n-tile0 {x0,x2}, n-tile1 {x1,x3}
            const int krow = ks * 16 + ((lm & 2) ? 8 : 0) + lr;
            const int tcol = (tw << 6) + (p << 4) + ((lm & 1) ? 8 : 0);
            uint32_t xh[4];
            LDSM4T(xh, sb + XH_OFF + (uint32_t)krow * 272u + (uint32_t)tcol * 2u);
            MMA_R(c[2 * p],     wh[0], wh[2], wh[1], wh[3], xh[0], xh[2]);
            MMA_R(c[2 * p + 1], wh[0], wh[2], wh[1], wh[3], xh[1], xh[3]);
        }
    }

    // ---- Epilogue: shfl-repair -> one STG.128 per n-tile, no smem ----
    //   lane^1 exchange: even lane i assembles (c0,c1,o0,o1) = row g,   t 4(i/2)..+3
    //                    odd  lane i assembles (o2,o3,c2,c3) = row g+8, t 4(i/2)..+3
    {
        const int row0 = (ow << 4) + g;
        const int tbase = (tw << 6) + ((iq >> 1) << 2);
        const bool evn = (iq & 1) == 0;
        float* op = og + (size_t)(evn ? row0 : row0 + 8) * T_DIM + tbase;
        #pragma unroll
        for (int nt = 0; nt < 8; nt++) {
            const float o0 = __shfl_xor_sync(0xFFFFFFFFu, c[nt][0], 1);
            const float o1 = __shfl_xor_sync(0xFFFFFFFFu, c[nt][1], 1);
            const float o2 = __shfl_xor_sync(0xFFFFFFFFu, c[nt][2], 1);
            const float o3 = __shfl_xor_sync(0xFFFFFFFFu, c[nt][3], 1);
            float4 v;
            if (evn) { v.x = c[nt][0]; v.y = c[nt][1]; v.z = o0; v.w = o1; }
            else     { v.x = o2;       v.y = o3;       v.z = c[nt][2]; v.w = c[nt][3]; }
            *(float4*)(op + nt * 8) = v;
        }
    }
}

extern "C" void kernel_launch(void* const* d_in, const int* in_sizes, int n_in,
                              void* d_out, int out_size) {
    const float* x = (const float*)d_in[0];   // [E, 64, 256]
    const float* W = (const float*)d_in[1];   // [E, 64, 64]
    const float* b = (const float*)d_in[2];   // [E, 64]
    float*       o = (float*)d_out;           // [E, 64, 256]

    const int E = in_sizes[0] / (K_DIM * T_DIM);

    cudaFuncSetAttribute(pl_hmma_shfl_kernel,
                         cudaFuncAttributeMaxDynamicSharedMemorySize, SMEM_BYTES);
    pl_hmma_shfl_kernel<<<2 * E, 256, SMEM_BYTES>>>(x, W, b, o);
}